// round 15
// baseline (speedup 1.0000x reference)
#include <cuda_runtime.h>
#include <cuda_fp16.h>
#include <cstdint>

// B=2, S=4096, D=4096, N_HEADS=2, HEAD_DIM=2048.
// RoPE cancels in q.k (same-angle pairwise rotation preserves dot products);
// causal row0 => ctx head0 == v0. Pipeline:
//   GEMM1: C1[8192 x 10240] = x @ [Wk;Wv;Wq1]^T  (fp16 in, fp32 out, HMMA)
//   attn : per-position 2-way causal softmax -> ctx in scrambled layout (fp16)
//   GEMM2: out[8192 x 4096] = ctx2d @ Wo^T (fp32 -> d_out)
// tcgen05 unusable (harness PTX target is sm_103, not sm_103a) -> mma.sync.
// R13->R14: warp tile 32x64 -> 64x64 (4 warps/CTA): -33% smem reads, -33% ldsm.

// ---------------- static device scratch (no allocation allowed) -------------
__device__ __align__(16) __half g_xh  [(size_t)8192 * 4096];   //  64 MB
__device__ __align__(16) __half g_wcat[(size_t)10240 * 4096];  //  80 MB  rows: [0,4096)=Wk, [4096,8192)=Wv, [8192,10240)=Wq[2048:]
__device__ __align__(16) __half g_woh [(size_t)4096 * 4096];   //  32 MB
__device__ __align__(16) float  g_c1  [(size_t)8192 * 10240];  // 320 MB  cols: k0,k1,v0,v1,q1
__device__ __align__(16) __half g_ctxh[(size_t)8192 * 4096];   //  64 MB

// ---------------- fp32 -> fp16 conversion ----------------------------------
__global__ void f2h_kernel(const float4* __restrict__ src, int dstSel,
                           size_t dstOff, int n4) {
    __half* dp = (dstSel == 0 ? g_xh : dstSel == 1 ? g_wcat : g_woh) + dstOff;
    int i = blockIdx.x * blockDim.x + threadIdx.x;
    if (i < n4) {
        float4 v = src[i];
        __half2* o = (__half2*)dp + 2 * (size_t)i;
        o[0] = __floats2half2_rn(v.x, v.y);
        o[1] = __floats2half2_rn(v.z, v.w);
    }
}

// ---------------- GEMM: C[m,n] = sum_k A[m,k]*B[n,k], fp16 x fp16 -> fp32 ---
// 128x128 tile, BK=64, 3 stages, 128 threads (4 warps), warp tile 64x64.
#define BM 128
#define BN 128
#define BK 64
#define STAGES 3
#define STAGE_BYTES 16384  // 128 rows * 128 B (64 fp16/row)

__device__ __forceinline__ uint32_t swz(int row, int kc) {
    // 128B rows, 8 x 16B chunks: XOR swizzle, conflict-free for cp.async
    // 16B stores and ldmatrix.x4 reads
    return (uint32_t)(row * 128 + ((kc ^ (row & 7)) << 4));
}
__device__ __forceinline__ void cp16(uint32_t dst, const void* src) {
    asm volatile("cp.async.cg.shared.global [%0], [%1], 16;\n" :: "r"(dst), "l"(src));
}
__device__ __forceinline__ void cp_commit() {
    asm volatile("cp.async.commit_group;\n");
}
__device__ __forceinline__ void ldsm4(uint32_t* r, uint32_t a) {
    asm volatile("ldmatrix.sync.aligned.m8n8.x4.shared.b16 {%0,%1,%2,%3}, [%4];\n"
                 : "=r"(r[0]), "=r"(r[1]), "=r"(r[2]), "=r"(r[3]) : "r"(a));
}
__device__ __forceinline__ void mma16816(float* c, const uint32_t* a,
                                         uint32_t b0, uint32_t b1) {
    asm volatile(
        "mma.sync.aligned.m16n8k16.row.col.f32.f16.f16.f32 "
        "{%0,%1,%2,%3}, {%4,%5,%6,%7}, {%8,%9}, {%0,%1,%2,%3};\n"
        : "+f"(c[0]), "+f"(c[1]), "+f"(c[2]), "+f"(c[3])
        : "r"(a[0]), "r"(a[1]), "r"(a[2]), "r"(a[3]), "r"(b0), "r"(b1));
}

__global__ void __launch_bounds__(128, 2)
gemm_kernel(int mode, float* __restrict__ Cext, int N, int K) {
    extern __shared__ __align__(16) char dsm[];
    const __half* __restrict__ A  = (mode == 0) ? g_xh   : g_ctxh;
    const __half* __restrict__ Bp = (mode == 0) ? g_wcat : g_woh;
    float* __restrict__ C         = (mode == 0) ? g_c1   : Cext;

    const int tid  = threadIdx.x;
    const int lane = tid & 31;
    const int warp = tid >> 5;
    const int wm = warp >> 1;  // 0..1
    const int wn = warp & 1;   // 0..1

    const int mBase = blockIdx.y * BM;
    const int nBase = blockIdx.x * BN;

    const uint32_t sAb = (uint32_t)__cvta_generic_to_shared(dsm);
    const uint32_t sBb = sAb + STAGES * STAGE_BYTES;

    // global->shared: 1024 16B chunks per operand per stage; 8 per thread.
    const int ldRow = tid >> 3;  // 0..15 (+16 per i)
    const int ldKc  = tid & 7;
    const __half* aSrc = A  + (size_t)(mBase + ldRow) * K + ldKc * 8;
    const __half* bSrc = Bp + (size_t)(nBase + ldRow) * K + ldKc * 8;
    uint32_t dsts[8];
#pragma unroll
    for (int i = 0; i < 8; i++) dsts[i] = swz(ldRow + 16 * i, ldKc);

    const int KT = K >> 6;  // K / 64

    float acc[4][8][4];
#pragma unroll
    for (int mt = 0; mt < 4; mt++)
#pragma unroll
        for (int j = 0; j < 8; j++)
#pragma unroll
            for (int e = 0; e < 4; e++) acc[mt][j][e] = 0.f;

    // prologue: stages 0..STAGES-2
#pragma unroll
    for (int s = 0; s < STAGES - 1; s++) {
        const __half* aS = aSrc + s * BK;
        const __half* bS = bSrc + s * BK;
#pragma unroll
        for (int i = 0; i < 8; i++)
            cp16(sAb + s * STAGE_BYTES + dsts[i], aS + (size_t)(16 * i) * K);
#pragma unroll
        for (int i = 0; i < 8; i++)
            cp16(sBb + s * STAGE_BYTES + dsts[i], bS + (size_t)(16 * i) * K);
        cp_commit();
    }

    const int lr16 = lane & 15;
    const int aRow[4] = { wm * 64 + lr16,      wm * 64 + 16 + lr16,
                          wm * 64 + 32 + lr16, wm * 64 + 48 + lr16 };
    const int bRow[4] = { wn * 64 + lr16,      wn * 64 + 16 + lr16,
                          wn * 64 + 32 + lr16, wn * 64 + 48 + lr16 };
    const int hiK = lane >> 4;  // 0/1 -> low/high 16B chunk of the k16

    for (int kt = 0; kt < KT; kt++) {
        asm volatile("cp.async.wait_group %0;\n" :: "n"(STAGES - 2));
        __syncthreads();

        const int nk = kt + STAGES - 1;
        if (nk < KT) {
            const int nst = nk % STAGES;
            const __half* aS = aSrc + nk * BK;
            const __half* bS = bSrc + nk * BK;
#pragma unroll
            for (int i = 0; i < 8; i++)
                cp16(sAb + nst * STAGE_BYTES + dsts[i], aS + (size_t)(16 * i) * K);
#pragma unroll
            for (int i = 0; i < 8; i++)
                cp16(sBb + nst * STAGE_BYTES + dsts[i], bS + (size_t)(16 * i) * K);
        }
        cp_commit();

        const int st = kt % STAGES;
        const uint32_t aBase = sAb + st * STAGE_BYTES;
        const uint32_t bBase = sBb + st * STAGE_BYTES;
#pragma unroll
        for (int ks = 0; ks < 4; ks++) {   // 4 x k16 = BK 64
            const int kc = ks * 2 + hiK;
            uint32_t af[4][4];
#pragma unroll
            for (int mt = 0; mt < 4; mt++)
                ldsm4(af[mt], aBase + swz(aRow[mt], kc));
            uint32_t bf[4][4];
#pragma unroll
            for (int p = 0; p < 4; p++)
                ldsm4(bf[p], bBase + swz(bRow[p], kc));
#pragma unroll
            for (int mt = 0; mt < 4; mt++)
#pragma unroll
                for (int p = 0; p < 4; p++) {
                    mma16816(acc[mt][2 * p],     af[mt], bf[p][0], bf[p][2]);
                    mma16816(acc[mt][2 * p + 1], af[mt], bf[p][1], bf[p][3]);
                }
        }
    }

    // epilogue: c0,c1 @ (row=lane/4, col=(lane%4)*2), c2,c3 @ row+8
    const int lr = lane >> 2;
    const int lc = (lane & 3) * 2;
#pragma unroll
    for (int mt = 0; mt < 4; mt++) {
        const int r = mBase + wm * 64 + mt * 16 + lr;
#pragma unroll
        for (int j = 0; j < 8; j++) {
            const int c = nBase + wn * 64 + j * 8 + lc;
            *(float2*)(C + (size_t)r * N + c) =
                make_float2(acc[mt][j][0], acc[mt][j][1]);
            *(float2*)(C + (size_t)(r + 8) * N + c) =
                make_float2(acc[mt][j][2], acc[mt][j][3]);
        }
    }
}

// ---------------- attention (2x2 causal, per-position) + scatter ------------
// C1 columns: [0,2048)=k0 [2048,4096)=k1 [4096,6144)=v0 [6144,8192)=v1 [8192,10240)=q1
__global__ void __launch_bounds__(256) attn_kernel() {
    const int m = blockIdx.x;           // b*4096 + s
    const float* base = g_c1 + (size_t)m * 10240;
    const int tid = threadIdx.x;

    const float4* q4  = (const float4*)(base + 8192);
    const float4* k04 = (const float4*)(base);
    const float4* k14 = (const float4*)(base + 2048);

    float d10 = 0.f, d11 = 0.f;
#pragma unroll
    for (int i = tid; i < 512; i += 256) {
        float4 q = q4[i], a = k04[i], b = k14[i];
        d10 += q.x * a.x + q.y * a.y + q.z * a.z + q.w * a.w;
        d11 += q.x * b.x + q.y * b.y + q.z * b.z + q.w * b.w;
    }
#pragma unroll
    for (int o = 16; o > 0; o >>= 1) {
        d10 += __shfl_xor_sync(0xffffffffu, d10, o);
        d11 += __shfl_xor_sync(0xffffffffu, d11, o);
    }
    __shared__ float s10s[8], s11s[8];
    __shared__ float sa0, sa1;
    if ((tid & 31) == 0) { s10s[tid >> 5] = d10; s11s[tid >> 5] = d11; }
    __syncthreads();
    if (tid == 0) {
        float t10 = 0.f, t11 = 0.f;
#pragma unroll
        for (int w = 0; w < 8; w++) { t10 += s10s[w]; t11 += s11s[w]; }
        const float sc = 0.022097086912079608f;  // 1/sqrt(2048)
        float x10 = t10 * sc, x11 = t11 * sc;
        float mx = fmaxf(x10, x11);
        float e0 = expf(x10 - mx), e1 = expf(x11 - mx);
        float inv = 1.f / (e0 + e1);
        sa0 = e0 * inv; sa1 = e1 * inv;
    }
    __syncthreads();
    const float a0 = sa0, a1 = sa1;

    const int b = m >> 12, s = m & 4095;
    // ctx2d[b, h*2048 + s/2, (s&1)*2048 + d]
    const size_t o0 = (((size_t)b * 4096 + (s >> 1)) * 4096) + (size_t)(s & 1) * 2048;
    const size_t o1 = o0 + (size_t)2048 * 4096;

    const float4* v04 = (const float4*)(base + 4096);
    const float4* v14 = (const float4*)(base + 6144);
#pragma unroll
    for (int i = tid; i < 512; i += 256) {
        float4 v0 = v04[i], v1 = v14[i];
        __half2* p0 = (__half2*)(g_ctxh + o0 + (size_t)i * 4);
        p0[0] = __floats2half2_rn(v0.x, v0.y);
        p0[1] = __floats2half2_rn(v0.z, v0.w);
        __half2* p1 = (__half2*)(g_ctxh + o1 + (size_t)i * 4);
        p1[0] = __floats2half2_rn(a0 * v0.x + a1 * v1.x, a0 * v0.y + a1 * v1.y);
        p1[1] = __floats2half2_rn(a0 * v0.z + a1 * v1.z, a0 * v0.w + a1 * v1.w);
    }
}

// ---------------- launch -----------------------------------------------------
#define SMEM_DYN (STAGES * STAGE_BYTES * 2)  // 98304 B

extern "C" void kernel_launch(void* const* d_in, const int* in_sizes, int n_in,
                              void* d_out, int out_size) {
    (void)in_sizes; (void)n_in; (void)out_size;
    const float* x  = (const float*)d_in[0];
    const float* Wq = (const float*)d_in[1];
    const float* Wk = (const float*)d_in[2];
    const float* Wv = (const float*)d_in[3];
    const float* Wo = (const float*)d_in[4];

    static int smemSet = 0;
    if (!smemSet) {
        cudaFuncSetAttribute(gemm_kernel,
                             cudaFuncAttributeMaxDynamicSharedMemorySize, SMEM_DYN);
        smemSet = 1;
    }

    // fp32 -> fp16 packs
    {
        int n4 = (2 * 4096 * 4096) / 4;  // x
        f2h_kernel<<<n4 / 256, 256>>>((const float4*)x, 0, 0, n4);
        n4 = (4096 * 4096) / 4;
        f2h_kernel<<<n4 / 256, 256>>>((const float4*)Wk, 1, 0, n4);
        f2h_kernel<<<n4 / 256, 256>>>((const float4*)Wv, 1, (size_t)4096 * 4096, n4);
        f2h_kernel<<<n4 / 256, 256>>>((const float4*)Wo, 2, 0, n4);
        n4 = (2048 * 4096) / 4;          // Wq head 1 only
        f2h_kernel<<<n4 / 256, 256>>>((const float4*)(Wq + (size_t)2048 * 4096), 1,
                                      (size_t)8192 * 4096, n4);
    }

    // GEMM1: [8192 x 4096] @ [10240 x 4096]^T -> k|v|q1 (fp32)
    gemm_kernel<<<dim3(10240 / BN, 8192 / BM), 128, SMEM_DYN>>>(0, nullptr, 10240, 4096);

    // per-position 2-head causal attention + scrambled ctx (fp16)
    attn_kernel<<<8192, 256>>>();

    // GEMM2: ctx2d @ Wo^T -> d_out (fp32)
    gemm_kernel<<<dim3(4096 / BN, 8192 / BM), 128, SMEM_DYN>>>(1, (float*)d_out, 4096, 4096);
}

// round 16
// speedup vs baseline: 1.0165x; 1.0165x over previous
#include <cuda_runtime.h>
#include <cuda_fp16.h>
#include <cstdint>

// B=2, S=4096, D=4096, N_HEADS=2, HEAD_DIM=2048.
// RoPE cancels in q.k (same-angle pairwise rotation preserves dot products);
// causal row0 => ctx head0 == v0. Pipeline:
//   GEMM1: C1h[8192 x 10240] = x @ [Wk;Wv;Wq1]^T  (fp16 in, fp32 acc, fp16 out)
//   attn : per-position 2-way causal softmax -> ctx in scrambled layout (fp16)
//   GEMM2: out[8192 x 4096] = ctx2d @ Wo^T (fp32 -> d_out)
// tcgen05 unusable (harness PTX target is sm_103, not sm_103a) -> mma.sync.
// R15->R16: revert to R13 mainloop (32x64 warp tile, 256thr, 2 CTA/SM);
//           C1 stored fp16 (-320MB round trip), attn vectorized on fp16.

// ---------------- static device scratch (no allocation allowed) -------------
__device__ __align__(16) __half g_xh  [(size_t)8192 * 4096];   //  64 MB
__device__ __align__(16) __half g_wcat[(size_t)10240 * 4096];  //  80 MB  rows: [0,4096)=Wk, [4096,8192)=Wv, [8192,10240)=Wq[2048:]
__device__ __align__(16) __half g_woh [(size_t)4096 * 4096];   //  32 MB
__device__ __align__(16) __half g_c1h [(size_t)8192 * 10240];  // 160 MB  cols: k0,k1,v0,v1,q1
__device__ __align__(16) __half g_ctxh[(size_t)8192 * 4096];   //  64 MB

// ---------------- fp32 -> fp16 conversion ----------------------------------
__global__ void f2h_kernel(const float4* __restrict__ src, int dstSel,
                           size_t dstOff, int n4) {
    __half* dp = (dstSel == 0 ? g_xh : dstSel == 1 ? g_wcat : g_woh) + dstOff;
    int i = blockIdx.x * blockDim.x + threadIdx.x;
    if (i < n4) {
        float4 v = src[i];
        __half2* o = (__half2*)dp + 2 * (size_t)i;
        o[0] = __floats2half2_rn(v.x, v.y);
        o[1] = __floats2half2_rn(v.z, v.w);
    }
}

// ---------------- GEMM: C[m,n] = sum_k A[m,k]*B[n,k], fp16 x fp16 -> fp32 ---
// 128x128 tile, BK=64, 3 stages, 256 threads, warp tile 32x64 (R13 config).
#define BM 128
#define BN 128
#define BK 64
#define STAGES 3
#define STAGE_BYTES 16384  // 128 rows * 128 B (64 fp16/row)

__device__ __forceinline__ uint32_t swz(int row, int kc) {
    // 128B rows, 8 x 16B chunks: XOR swizzle, conflict-free for cp.async
    // 16B stores and ldmatrix.x4 reads
    return (uint32_t)(row * 128 + ((kc ^ (row & 7)) << 4));
}
__device__ __forceinline__ void cp16(uint32_t dst, const void* src) {
    asm volatile("cp.async.cg.shared.global [%0], [%1], 16;\n" :: "r"(dst), "l"(src));
}
__device__ __forceinline__ void cp_commit() {
    asm volatile("cp.async.commit_group;\n");
}
__device__ __forceinline__ void ldsm4(uint32_t* r, uint32_t a) {
    asm volatile("ldmatrix.sync.aligned.m8n8.x4.shared.b16 {%0,%1,%2,%3}, [%4];\n"
                 : "=r"(r[0]), "=r"(r[1]), "=r"(r[2]), "=r"(r[3]) : "r"(a));
}
__device__ __forceinline__ void mma16816(float* c, const uint32_t* a,
                                         uint32_t b0, uint32_t b1) {
    asm volatile(
        "mma.sync.aligned.m16n8k16.row.col.f32.f16.f16.f32 "
        "{%0,%1,%2,%3}, {%4,%5,%6,%7}, {%8,%9}, {%0,%1,%2,%3};\n"
        : "+f"(c[0]), "+f"(c[1]), "+f"(c[2]), "+f"(c[3])
        : "r"(a[0]), "r"(a[1]), "r"(a[2]), "r"(a[3]), "r"(b0), "r"(b1));
}

__global__ void __launch_bounds__(256, 2)
gemm_kernel(int mode, float* __restrict__ Cext, int N, int K) {
    extern __shared__ __align__(16) char dsm[];
    const __half* __restrict__ A  = (mode == 0) ? g_xh   : g_ctxh;
    const __half* __restrict__ Bp = (mode == 0) ? g_wcat : g_woh;

    const int tid  = threadIdx.x;
    const int lane = tid & 31;
    const int warp = tid >> 5;
    const int wm = warp >> 1;  // 0..3 (m)
    const int wn = warp & 1;   // 0..1 (n)

    const int mBase = blockIdx.y * BM;
    const int nBase = blockIdx.x * BN;

    const uint32_t sAb = (uint32_t)__cvta_generic_to_shared(dsm);
    const uint32_t sBb = sAb + STAGES * STAGE_BYTES;

    // global->shared: 1024 16B-chunks per tile per operand; 4 chunks/thread.
    const int ldRow = tid >> 3;       // 0..31 (+32*i)
    const int ldKc  = tid & 7;
    const __half* aSrc = A  + (size_t)(mBase + ldRow) * K + ldKc * 8;
    const __half* bSrc = Bp + (size_t)(nBase + ldRow) * K + ldKc * 8;
    uint32_t dsts[4];
#pragma unroll
    for (int i = 0; i < 4; i++) dsts[i] = swz(ldRow + 32 * i, ldKc);

    const int KT = K >> 6;  // K / 64

    float acc[2][8][4];
#pragma unroll
    for (int mt = 0; mt < 2; mt++)
#pragma unroll
        for (int j = 0; j < 8; j++)
#pragma unroll
            for (int e = 0; e < 4; e++) acc[mt][j][e] = 0.f;

    // prologue: stages 0..STAGES-2
#pragma unroll
    for (int s = 0; s < STAGES - 1; s++) {
        const __half* aS = aSrc + s * BK;
        const __half* bS = bSrc + s * BK;
#pragma unroll
        for (int i = 0; i < 4; i++) {
            cp16(sAb + s * STAGE_BYTES + dsts[i], aS + (size_t)(32 * i) * K);
            cp16(sBb + s * STAGE_BYTES + dsts[i], bS + (size_t)(32 * i) * K);
        }
        cp_commit();
    }

    const int aRow[2] = { wm * 32 + (lane & 15), wm * 32 + 16 + (lane & 15) };
    const int bRow[4] = { wn * 64 + (lane & 15),      wn * 64 + 16 + (lane & 15),
                          wn * 64 + 32 + (lane & 15), wn * 64 + 48 + (lane & 15) };
    const int hiK = lane >> 4;  // 0/1 -> low/high 16B chunk of the k16

    for (int kt = 0; kt < KT; kt++) {
        asm volatile("cp.async.wait_group %0;\n" :: "n"(STAGES - 2));
        __syncthreads();

        const int nk = kt + STAGES - 1;
        if (nk < KT) {
            const int nst = nk % STAGES;
            const __half* aS = aSrc + nk * BK;
            const __half* bS = bSrc + nk * BK;
#pragma unroll
            for (int i = 0; i < 4; i++) {
                cp16(sAb + nst * STAGE_BYTES + dsts[i], aS + (size_t)(32 * i) * K);
                cp16(sBb + nst * STAGE_BYTES + dsts[i], bS + (size_t)(32 * i) * K);
            }
        }
        cp_commit();

        const int st = kt % STAGES;
        const uint32_t aBase = sAb + st * STAGE_BYTES;
        const uint32_t bBase = sBb + st * STAGE_BYTES;
#pragma unroll
        for (int ks = 0; ks < 4; ks++) {   // 4 x k16 = BK 64
            const int kc = ks * 2 + hiK;
            uint32_t af[2][4];
#pragma unroll
            for (int mt = 0; mt < 2; mt++)
                ldsm4(af[mt], aBase + swz(aRow[mt], kc));
            uint32_t bf[4][4];
#pragma unroll
            for (int p = 0; p < 4; p++)
                ldsm4(bf[p], bBase + swz(bRow[p], kc));
#pragma unroll
            for (int mt = 0; mt < 2; mt++)
#pragma unroll
                for (int p = 0; p < 4; p++) {
                    mma16816(acc[mt][2 * p],     af[mt], bf[p][0], bf[p][2]);
                    mma16816(acc[mt][2 * p + 1], af[mt], bf[p][1], bf[p][3]);
                }
        }
    }

    // epilogue: c0,c1 @ (row=lane/4, col=(lane%4)*2), c2,c3 @ row+8
    const int lr = lane >> 2;
    const int lc = (lane & 3) * 2;
    if (mode == 0) {
        // fp16 store to g_c1h
#pragma unroll
        for (int mt = 0; mt < 2; mt++) {
            const int r = mBase + wm * 32 + mt * 16 + lr;
#pragma unroll
            for (int j = 0; j < 8; j++) {
                const int c = nBase + wn * 64 + j * 8 + lc;
                *(__half2*)(g_c1h + (size_t)r * N + c) =
                    __floats2half2_rn(acc[mt][j][0], acc[mt][j][1]);
                *(__half2*)(g_c1h + (size_t)(r + 8) * N + c) =
                    __floats2half2_rn(acc[mt][j][2], acc[mt][j][3]);
            }
        }
    } else {
        // fp32 store to d_out
#pragma unroll
        for (int mt = 0; mt < 2; mt++) {
            const int r = mBase + wm * 32 + mt * 16 + lr;
#pragma unroll
            for (int j = 0; j < 8; j++) {
                const int c = nBase + wn * 64 + j * 8 + lc;
                *(float2*)(Cext + (size_t)r * N + c) =
                    make_float2(acc[mt][j][0], acc[mt][j][1]);
                *(float2*)(Cext + (size_t)(r + 8) * N + c) =
                    make_float2(acc[mt][j][2], acc[mt][j][3]);
            }
        }
    }
}

// ---------------- attention (2x2 causal, per-position) + scatter ------------
// C1h columns: [0,2048)=k0 [2048,4096)=k1 [4096,6144)=v0 [6144,8192)=v1 [8192,10240)=q1
// 2048 halves per section = 256 x 16B chunks; one chunk per thread.
__global__ void __launch_bounds__(256) attn_kernel() {
    const int m = blockIdx.x;           // b*4096 + s
    const __half* base = g_c1h + (size_t)m * 10240;
    const int tid = threadIdx.x;

    const uint4 qv  = ((const uint4*)(base + 8192))[tid];
    const uint4 k0v = ((const uint4*)(base))[tid];
    const uint4 k1v = ((const uint4*)(base + 2048))[tid];

    float d10 = 0.f, d11 = 0.f;
    const __half2* qh  = (const __half2*)&qv;
    const __half2* k0h = (const __half2*)&k0v;
    const __half2* k1h = (const __half2*)&k1v;
#pragma unroll
    for (int j = 0; j < 4; j++) {
        float2 q = __half22float2(qh[j]);
        float2 a = __half22float2(k0h[j]);
        float2 b = __half22float2(k1h[j]);
        d10 += q.x * a.x + q.y * a.y;
        d11 += q.x * b.x + q.y * b.y;
    }
#pragma unroll
    for (int o = 16; o > 0; o >>= 1) {
        d10 += __shfl_xor_sync(0xffffffffu, d10, o);
        d11 += __shfl_xor_sync(0xffffffffu, d11, o);
    }
    __shared__ float s10s[8], s11s[8];
    __shared__ float sa0, sa1;
    if ((tid & 31) == 0) { s10s[tid >> 5] = d10; s11s[tid >> 5] = d11; }
    __syncthreads();
    if (tid == 0) {
        float t10 = 0.f, t11 = 0.f;
#pragma unroll
        for (int w = 0; w < 8; w++) { t10 += s10s[w]; t11 += s11s[w]; }
        const float sc = 0.022097086912079608f;  // 1/sqrt(2048)
        float x10 = t10 * sc, x11 = t11 * sc;
        float mx = fmaxf(x10, x11);
        float e0 = expf(x10 - mx), e1 = expf(x11 - mx);
        float inv = 1.f / (e0 + e1);
        sa0 = e0 * inv; sa1 = e1 * inv;
    }
    __syncthreads();
    const float a0 = sa0, a1 = sa1;

    const int b = m >> 12, s = m & 4095;
    // ctx2d[b, h*2048 + s/2, (s&1)*2048 + d]
    const size_t o0 = (((size_t)b * 4096 + (s >> 1)) * 4096) + (size_t)(s & 1) * 2048;
    const size_t o1 = o0 + (size_t)2048 * 4096;

    const uint4 v0v = ((const uint4*)(base + 4096))[tid];
    const uint4 v1v = ((const uint4*)(base + 6144))[tid];

    // head0: ctx == v0 exactly (causal row 0)
    *(uint4*)(g_ctxh + o0 + (size_t)tid * 8) = v0v;

    // head1: a0*v0 + a1*v1
    const __half2* v0h = (const __half2*)&v0v;
    const __half2* v1h = (const __half2*)&v1v;
    uint4 outv;
    __half2* oh = (__half2*)&outv;
#pragma unroll
    for (int j = 0; j < 4; j++) {
        float2 f0 = __half22float2(v0h[j]);
        float2 f1 = __half22float2(v1h[j]);
        oh[j] = __floats2half2_rn(a0 * f0.x + a1 * f1.x, a0 * f0.y + a1 * f1.y);
    }
    *(uint4*)(g_ctxh + o1 + (size_t)tid * 8) = outv;
}

// ---------------- launch -----------------------------------------------------
#define SMEM_DYN (STAGES * STAGE_BYTES * 2)  // 98304 B

extern "C" void kernel_launch(void* const* d_in, const int* in_sizes, int n_in,
                              void* d_out, int out_size) {
    (void)in_sizes; (void)n_in; (void)out_size;
    const float* x  = (const float*)d_in[0];
    const float* Wq = (const float*)d_in[1];
    const float* Wk = (const float*)d_in[2];
    const float* Wv = (const float*)d_in[3];
    const float* Wo = (const float*)d_in[4];

    static int smemSet = 0;
    if (!smemSet) {
        cudaFuncSetAttribute(gemm_kernel,
                             cudaFuncAttributeMaxDynamicSharedMemorySize, SMEM_DYN);
        smemSet = 1;
    }

    // fp32 -> fp16 packs
    {
        int n4 = (2 * 4096 * 4096) / 4;  // x
        f2h_kernel<<<n4 / 256, 256>>>((const float4*)x, 0, 0, n4);
        n4 = (4096 * 4096) / 4;
        f2h_kernel<<<n4 / 256, 256>>>((const float4*)Wk, 1, 0, n4);
        f2h_kernel<<<n4 / 256, 256>>>((const float4*)Wv, 1, (size_t)4096 * 4096, n4);
        f2h_kernel<<<n4 / 256, 256>>>((const float4*)Wo, 2, 0, n4);
        n4 = (2048 * 4096) / 4;          // Wq head 1 only
        f2h_kernel<<<n4 / 256, 256>>>((const float4*)(Wq + (size_t)2048 * 4096), 1,
                                      (size_t)8192 * 4096, n4);
    }

    // GEMM1: [8192 x 4096] @ [10240 x 4096]^T -> k|v|q1 (fp16 out)
    gemm_kernel<<<dim3(10240 / BN, 8192 / BM), 256, SMEM_DYN>>>(0, nullptr, 10240, 4096);

    // per-position 2-head causal attention + scrambled ctx (fp16)
    attn_kernel<<<8192, 256>>>();

    // GEMM2: ctx2d @ Wo^T -> d_out (fp32)
    gemm_kernel<<<dim3(4096 / BN, 8192 / BM), 256, SMEM_DYN>>>(1, (float*)d_out, 4096, 4096);
}

// round 17
// speedup vs baseline: 1.0371x; 1.0203x over previous
#include <cuda_runtime.h>
#include <cuda_fp16.h>
#include <cstdint>

// B=2, S=4096, D=4096, N_HEADS=2, HEAD_DIM=2048.
// RoPE cancels in q.k (same-angle pairwise rotation preserves dot products);
// causal row0 => ctx head0 == v0. Pipeline:
//   GEMM1: C1h[8192 x 10240] = x @ [Wk;Wv;Wq1]^T  (fp16 in, fp32 acc, fp16 out)
//   attn : per-position 2-way causal softmax -> ctx in scrambled layout (fp16)
//   GEMM2: out[8192 x 4096] = ctx2d @ Wo^T (fp32 -> d_out)
// tcgen05 unusable (harness PTX target is sm_103, not sm_103a) -> mma.sync.
// R16->R17: GEMM split into template instantiations (one epilogue each, no
//           runtime branch -> R13 register allocation); f2h widened to
//           32B-read/16B-store per thread.

// ---------------- static device scratch (no allocation allowed) -------------
__device__ __align__(16) __half g_xh  [(size_t)8192 * 4096];   //  64 MB
__device__ __align__(16) __half g_wcat[(size_t)10240 * 4096];  //  80 MB  rows: [0,4096)=Wk, [4096,8192)=Wv, [8192,10240)=Wq[2048:]
__device__ __align__(16) __half g_woh [(size_t)4096 * 4096];   //  32 MB
__device__ __align__(16) __half g_c1h [(size_t)8192 * 10240];  // 160 MB  cols: k0,k1,v0,v1,q1
__device__ __align__(16) __half g_ctxh[(size_t)8192 * 4096];   //  64 MB

// ---------------- fp32 -> fp16 conversion (32B read / 16B store per thread) -
__global__ void f2h_kernel(const float4* __restrict__ src, int dstSel,
                           size_t dstOff, int n8) {
    __half* dp = (dstSel == 0 ? g_xh : dstSel == 1 ? g_wcat : g_woh) + dstOff;
    int i = blockIdx.x * blockDim.x + threadIdx.x;
    if (i < n8) {
        float4 v0 = src[2 * (size_t)i];
        float4 v1 = src[2 * (size_t)i + 1];
        uint4 o;
        __half2* oh = (__half2*)&o;
        oh[0] = __floats2half2_rn(v0.x, v0.y);
        oh[1] = __floats2half2_rn(v0.z, v0.w);
        oh[2] = __floats2half2_rn(v1.x, v1.y);
        oh[3] = __floats2half2_rn(v1.z, v1.w);
        *(uint4*)(dp + 8 * (size_t)i) = o;
    }
}

// ---------------- GEMM: C[m,n] = sum_k A[m,k]*B[n,k], fp16 x fp16 -> fp32 ---
// 128x128 tile, BK=64, 3 stages, 256 threads, warp tile 32x64 (R13 config).
#define BM 128
#define BN 128
#define BK 64
#define STAGES 3
#define STAGE_BYTES 16384  // 128 rows * 128 B (64 fp16/row)

__device__ __forceinline__ uint32_t swz(int row, int kc) {
    // 128B rows, 8 x 16B chunks: XOR swizzle, conflict-free for cp.async
    // 16B stores and ldmatrix.x4 reads
    return (uint32_t)(row * 128 + ((kc ^ (row & 7)) << 4));
}
__device__ __forceinline__ void cp16(uint32_t dst, const void* src) {
    asm volatile("cp.async.cg.shared.global [%0], [%1], 16;\n" :: "r"(dst), "l"(src));
}
__device__ __forceinline__ void cp_commit() {
    asm volatile("cp.async.commit_group;\n");
}
__device__ __forceinline__ void ldsm4(uint32_t* r, uint32_t a) {
    asm volatile("ldmatrix.sync.aligned.m8n8.x4.shared.b16 {%0,%1,%2,%3}, [%4];\n"
                 : "=r"(r[0]), "=r"(r[1]), "=r"(r[2]), "=r"(r[3]) : "r"(a));
}
__device__ __forceinline__ void mma16816(float* c, const uint32_t* a,
                                         uint32_t b0, uint32_t b1) {
    asm volatile(
        "mma.sync.aligned.m16n8k16.row.col.f32.f16.f16.f32 "
        "{%0,%1,%2,%3}, {%4,%5,%6,%7}, {%8,%9}, {%0,%1,%2,%3};\n"
        : "+f"(c[0]), "+f"(c[1]), "+f"(c[2]), "+f"(c[3])
        : "r"(a[0]), "r"(a[1]), "r"(a[2]), "r"(a[3]), "r"(b0), "r"(b1));
}

template <int MODE>
__global__ void __launch_bounds__(256, 2)
gemm_kernel(float* __restrict__ Cext, int N, int K) {
    extern __shared__ __align__(16) char dsm[];
    const __half* __restrict__ A  = (MODE == 0) ? g_xh   : g_ctxh;
    const __half* __restrict__ Bp = (MODE == 0) ? g_wcat : g_woh;

    const int tid  = threadIdx.x;
    const int lane = tid & 31;
    const int warp = tid >> 5;
    const int wm = warp >> 1;  // 0..3 (m)
    const int wn = warp & 1;   // 0..1 (n)

    const int mBase = blockIdx.y * BM;
    const int nBase = blockIdx.x * BN;

    const uint32_t sAb = (uint32_t)__cvta_generic_to_shared(dsm);
    const uint32_t sBb = sAb + STAGES * STAGE_BYTES;

    // global->shared: 1024 16B-chunks per tile per operand; 4 chunks/thread.
    const int ldRow = tid >> 3;       // 0..31 (+32*i)
    const int ldKc  = tid & 7;
    const __half* aSrc = A  + (size_t)(mBase + ldRow) * K + ldKc * 8;
    const __half* bSrc = Bp + (size_t)(nBase + ldRow) * K + ldKc * 8;
    uint32_t dsts[4];
#pragma unroll
    for (int i = 0; i < 4; i++) dsts[i] = swz(ldRow + 32 * i, ldKc);

    const int KT = K >> 6;  // K / 64

    float acc[2][8][4];
#pragma unroll
    for (int mt = 0; mt < 2; mt++)
#pragma unroll
        for (int j = 0; j < 8; j++)
#pragma unroll
            for (int e = 0; e < 4; e++) acc[mt][j][e] = 0.f;

    // prologue: stages 0..STAGES-2
#pragma unroll
    for (int s = 0; s < STAGES - 1; s++) {
        const __half* aS = aSrc + s * BK;
        const __half* bS = bSrc + s * BK;
#pragma unroll
        for (int i = 0; i < 4; i++) {
            cp16(sAb + s * STAGE_BYTES + dsts[i], aS + (size_t)(32 * i) * K);
            cp16(sBb + s * STAGE_BYTES + dsts[i], bS + (size_t)(32 * i) * K);
        }
        cp_commit();
    }

    const int aRow[2] = { wm * 32 + (lane & 15), wm * 32 + 16 + (lane & 15) };
    const int bRow[4] = { wn * 64 + (lane & 15),      wn * 64 + 16 + (lane & 15),
                          wn * 64 + 32 + (lane & 15), wn * 64 + 48 + (lane & 15) };
    const int hiK = lane >> 4;  // 0/1 -> low/high 16B chunk of the k16

    for (int kt = 0; kt < KT; kt++) {
        asm volatile("cp.async.wait_group %0;\n" :: "n"(STAGES - 2));
        __syncthreads();

        const int nk = kt + STAGES - 1;
        if (nk < KT) {
            const int nst = nk % STAGES;
            const __half* aS = aSrc + nk * BK;
            const __half* bS = bSrc + nk * BK;
#pragma unroll
            for (int i = 0; i < 4; i++) {
                cp16(sAb + nst * STAGE_BYTES + dsts[i], aS + (size_t)(32 * i) * K);
                cp16(sBb + nst * STAGE_BYTES + dsts[i], bS + (size_t)(32 * i) * K);
            }
        }
        cp_commit();

        const int st = kt % STAGES;
        const uint32_t aBase = sAb + st * STAGE_BYTES;
        const uint32_t bBase = sBb + st * STAGE_BYTES;
#pragma unroll
        for (int ks = 0; ks < 4; ks++) {   // 4 x k16 = BK 64
            const int kc = ks * 2 + hiK;
            uint32_t af[2][4];
#pragma unroll
            for (int mt = 0; mt < 2; mt++)
                ldsm4(af[mt], aBase + swz(aRow[mt], kc));
            uint32_t bf[4][4];
#pragma unroll
            for (int p = 0; p < 4; p++)
                ldsm4(bf[p], bBase + swz(bRow[p], kc));
#pragma unroll
            for (int mt = 0; mt < 2; mt++)
#pragma unroll
                for (int p = 0; p < 4; p++) {
                    mma16816(acc[mt][2 * p],     af[mt], bf[p][0], bf[p][2]);
                    mma16816(acc[mt][2 * p + 1], af[mt], bf[p][1], bf[p][3]);
                }
        }
    }

    // epilogue: c0,c1 @ (row=lane/4, col=(lane%4)*2), c2,c3 @ row+8
    const int lr = lane >> 2;
    const int lc = (lane & 3) * 2;
#pragma unroll
    for (int mt = 0; mt < 2; mt++) {
        const int r = mBase + wm * 32 + mt * 16 + lr;
#pragma unroll
        for (int j = 0; j < 8; j++) {
            const int c = nBase + wn * 64 + j * 8 + lc;
            if (MODE == 0) {
                *(__half2*)(g_c1h + (size_t)r * N + c) =
                    __floats2half2_rn(acc[mt][j][0], acc[mt][j][1]);
                *(__half2*)(g_c1h + (size_t)(r + 8) * N + c) =
                    __floats2half2_rn(acc[mt][j][2], acc[mt][j][3]);
            } else {
                *(float2*)(Cext + (size_t)r * N + c) =
                    make_float2(acc[mt][j][0], acc[mt][j][1]);
                *(float2*)(Cext + (size_t)(r + 8) * N + c) =
                    make_float2(acc[mt][j][2], acc[mt][j][3]);
            }
        }
    }
}

// ---------------- attention (2x2 causal, per-position) + scatter ------------
// C1h columns: [0,2048)=k0 [2048,4096)=k1 [4096,6144)=v0 [6144,8192)=v1 [8192,10240)=q1
// 2048 halves per section = 256 x 16B chunks; one chunk per thread.
__global__ void __launch_bounds__(256) attn_kernel() {
    const int m = blockIdx.x;           // b*4096 + s
    const __half* base = g_c1h + (size_t)m * 10240;
    const int tid = threadIdx.x;

    const uint4 qv  = ((const uint4*)(base + 8192))[tid];
    const uint4 k0v = ((const uint4*)(base))[tid];
    const uint4 k1v = ((const uint4*)(base + 2048))[tid];

    float d10 = 0.f, d11 = 0.f;
    const __half2* qh  = (const __half2*)&qv;
    const __half2* k0h = (const __half2*)&k0v;
    const __half2* k1h = (const __half2*)&k1v;
#pragma unroll
    for (int j = 0; j < 4; j++) {
        float2 q = __half22float2(qh[j]);
        float2 a = __half22float2(k0h[j]);
        float2 b = __half22float2(k1h[j]);
        d10 += q.x * a.x + q.y * a.y;
        d11 += q.x * b.x + q.y * b.y;
    }
#pragma unroll
    for (int o = 16; o > 0; o >>= 1) {
        d10 += __shfl_xor_sync(0xffffffffu, d10, o);
        d11 += __shfl_xor_sync(0xffffffffu, d11, o);
    }
    __shared__ float s10s[8], s11s[8];
    __shared__ float sa0, sa1;
    if ((tid & 31) == 0) { s10s[tid >> 5] = d10; s11s[tid >> 5] = d11; }
    __syncthreads();
    if (tid == 0) {
        float t10 = 0.f, t11 = 0.f;
#pragma unroll
        for (int w = 0; w < 8; w++) { t10 += s10s[w]; t11 += s11s[w]; }
        const float sc = 0.022097086912079608f;  // 1/sqrt(2048)
        float x10 = t10 * sc, x11 = t11 * sc;
        float mx = fmaxf(x10, x11);
        float e0 = expf(x10 - mx), e1 = expf(x11 - mx);
        float inv = 1.f / (e0 + e1);
        sa0 = e0 * inv; sa1 = e1 * inv;
    }
    __syncthreads();
    const float a0 = sa0, a1 = sa1;

    const int b = m >> 12, s = m & 4095;
    // ctx2d[b, h*2048 + s/2, (s&1)*2048 + d]
    const size_t o0 = (((size_t)b * 4096 + (s >> 1)) * 4096) + (size_t)(s & 1) * 2048;
    const size_t o1 = o0 + (size_t)2048 * 4096;

    const uint4 v0v = ((const uint4*)(base + 4096))[tid];
    const uint4 v1v = ((const uint4*)(base + 6144))[tid];

    // head0: ctx == v0 exactly (causal row 0)
    *(uint4*)(g_ctxh + o0 + (size_t)tid * 8) = v0v;

    // head1: a0*v0 + a1*v1
    const __half2* v0h = (const __half2*)&v0v;
    const __half2* v1h = (const __half2*)&v1v;
    uint4 outv;
    __half2* oh = (__half2*)&outv;
#pragma unroll
    for (int j = 0; j < 4; j++) {
        float2 f0 = __half22float2(v0h[j]);
        float2 f1 = __half22float2(v1h[j]);
        oh[j] = __floats2half2_rn(a0 * f0.x + a1 * f1.x, a0 * f0.y + a1 * f1.y);
    }
    *(uint4*)(g_ctxh + o1 + (size_t)tid * 8) = outv;
}

// ---------------- launch -----------------------------------------------------
#define SMEM_DYN (STAGES * STAGE_BYTES * 2)  // 98304 B

extern "C" void kernel_launch(void* const* d_in, const int* in_sizes, int n_in,
                              void* d_out, int out_size) {
    (void)in_sizes; (void)n_in; (void)out_size;
    const float* x  = (const float*)d_in[0];
    const float* Wq = (const float*)d_in[1];
    const float* Wk = (const float*)d_in[2];
    const float* Wv = (const float*)d_in[3];
    const float* Wo = (const float*)d_in[4];

    static int smemSet = 0;
    if (!smemSet) {
        cudaFuncSetAttribute(gemm_kernel<0>,
                             cudaFuncAttributeMaxDynamicSharedMemorySize, SMEM_DYN);
        cudaFuncSetAttribute(gemm_kernel<1>,
                             cudaFuncAttributeMaxDynamicSharedMemorySize, SMEM_DYN);
        smemSet = 1;
    }

    // fp32 -> fp16 packs (each thread: 32B read, 16B store)
    {
        int n8 = (2 * 4096 * 4096) / 8;  // x
        f2h_kernel<<<n8 / 256, 256>>>((const float4*)x, 0, 0, n8);
        n8 = (4096 * 4096) / 8;
        f2h_kernel<<<n8 / 256, 256>>>((const float4*)Wk, 1, 0, n8);
        f2h_kernel<<<n8 / 256, 256>>>((const float4*)Wv, 1, (size_t)4096 * 4096, n8);
        f2h_kernel<<<n8 / 256, 256>>>((const float4*)Wo, 2, 0, n8);
        n8 = (2048 * 4096) / 8;          // Wq head 1 only
        f2h_kernel<<<n8 / 256, 256>>>((const float4*)(Wq + (size_t)2048 * 4096), 1,
                                      (size_t)8192 * 4096, n8);
    }

    // GEMM1: [8192 x 4096] @ [10240 x 4096]^T -> k|v|q1 (fp16 out)
    gemm_kernel<0><<<dim3(10240 / BN, 8192 / BM), 256, SMEM_DYN>>>(nullptr, 10240, 4096);

    // per-position 2-head causal attention + scrambled ctx (fp16)
    attn_kernel<<<8192, 256>>>();

    // GEMM2: ctx2d @ Wo^T -> d_out (fp32)
    gemm_kernel<1><<<dim3(4096 / BN, 8192 / BM), 256, SMEM_DYN>>>((float*)d_out, 4096, 4096);
}